// round 16
// baseline (speedup 1.0000x reference)
#include <cuda_runtime.h>
#include <cuda_bf16.h>
#include <mma.h>
#include <cstdint>

using namespace nvcuda;

// Problem constants
#define NC     64          // channels
#define SS     3136        // 56*56
#define NIMG   128
#define MTOT   (NIMG*SS)   // 401408
#define KT     64          // s-tile width (gram)
#define TILES  (NIMG*49)   // 6272 tiles of 64 columns (gram)
#define GRID_G 296         // gram: one wave at 2 CTA/SM
#define GRID_W 444         // whiten: one wave at 3 CTA/SM
#define NWARPS (GRID_W*8)  // 3552 independent whiten warps
#define NSLICE (NIMG*196)  // 25088 slices of 64ch x 16s
#define BPITCH 72          // gram bf16 smem pitch
#define RPITCH 36          // gram reduction pitch
#define TPITCH 24          // whiten warp-tile bf16 pitch (48B rows)
#define EPSF   1e-3f

// Scratch (static device globals: allocation-free)
__device__ float          g_partials[GRID_G][4160]; // 4096 gram + 64 channel sums
__device__ float          g_G[4160];
__device__ float          g_mean[NC];
__device__ uint4          g_EpA[8][32];             // permuted E: b0 parts (kb=0..3)
__device__ uint4          g_EpB[8][32];             // permuted E: b1 parts (kb=0..3)

// ---------------------------------------------------------------------------
// PTX helpers (documented fragment layouts)
// ---------------------------------------------------------------------------
__device__ __forceinline__ void ldmatrix_x4_trans(uint32_t& r0, uint32_t& r1,
                                                  uint32_t& r2, uint32_t& r3,
                                                  uint32_t saddr) {
    asm volatile("ldmatrix.sync.aligned.m8n8.x4.trans.shared.b16 {%0,%1,%2,%3}, [%4];"
                 : "=r"(r0), "=r"(r1), "=r"(r2), "=r"(r3) : "r"(saddr));
}

__device__ __forceinline__ void mma16816(float& c0, float& c1, float& c2, float& c3,
                                         uint32_t a0, uint32_t a1, uint32_t a2, uint32_t a3,
                                         uint32_t b0, uint32_t b1) {
    asm volatile("mma.sync.aligned.m16n8k16.row.col.f32.bf16.bf16.f32 "
                 "{%0,%1,%2,%3},{%4,%5,%6,%7},{%8,%9},{%0,%1,%2,%3};"
                 : "+f"(c0), "+f"(c1), "+f"(c2), "+f"(c3)
                 : "r"(a0), "r"(a1), "r"(a2), "r"(a3), "r"(b0), "r"(b1));
}

__device__ __forceinline__ uint32_t pack_bf16x2(float lo, float hi) {
    __nv_bfloat162 p = __floats2bfloat162_rn(lo, hi);
    return *(uint32_t*)&p;
}

// ---------------------------------------------------------------------------
// Kernel 1: partial Gram + channel sums (unchanged: split-K warps, register
// prefetch, double buffer, one barrier per tile).
// ---------------------------------------------------------------------------
__global__ __launch_bounds__(256, 2) void gram_kernel(const float* __restrict__ X) {
    __shared__ __nv_bfloat16 tb[2][NC * BPITCH];
    __shared__ float sred[4][32 * RPITCH];
    __shared__ float ssum[NC];

    const int t = threadIdx.x, b = blockIdx.x;
    const int warp = t >> 5;
    const int row = t >> 2;
    const int c4  = (t & 3) * 4;

    const int khalf = warp >> 2;
    const int quad  = warp & 3;
    const int r0 = (quad >> 1) * 32;
    const int q0 = (quad & 1) * 32;
    const int k0 = khalf * 32;

    wmma::fragment<wmma::accumulator, 16, 16, 16, float> acc[2][2];
    #pragma unroll
    for (int i = 0; i < 2; ++i)
        #pragma unroll
        for (int j = 0; j < 2; ++j)
            wmma::fill_fragment(acc[i][j], 0.0f);

    float lsum = 0.0f;

    {
        const int n  = b / 49;
        const int s0 = (b % 49) * KT;
        const float4* src = (const float4*)(X + (size_t)n * NC * SS + (size_t)row * SS + s0);
        #pragma unroll
        for (int j = 0; j < 4; ++j) {
            float4 v = src[c4 + j];
            lsum += v.x + v.y + v.z + v.w;
            __nv_bfloat162* dst = (__nv_bfloat162*)&tb[0][row * BPITCH + (c4 + j) * 4];
            dst[0] = __floats2bfloat162_rn(v.x, v.y);
            dst[1] = __floats2bfloat162_rn(v.z, v.w);
        }
    }
    __syncthreads();

    int buf = 0;
    for (int T = b; T < TILES; T += GRID_G, buf ^= 1) {
        const int Tn = T + GRID_G;
        const bool has = (Tn < TILES);

        float4 w[4];
        if (has) {
            const int n  = Tn / 49;
            const int s0 = (Tn % 49) * KT;
            const float4* src = (const float4*)(X + (size_t)n * NC * SS + (size_t)row * SS + s0);
            #pragma unroll
            for (int j = 0; j < 4; ++j) w[j] = src[c4 + j];
        }

        #pragma unroll
        for (int k = 0; k < 2; ++k) {
            const int kk = k0 + k * 16;
            wmma::fragment<wmma::matrix_a, 16, 16, 16, __nv_bfloat16, wmma::row_major> fa0, fa1;
            wmma::fragment<wmma::matrix_b, 16, 16, 16, __nv_bfloat16, wmma::col_major> fb0, fb1;
            wmma::load_matrix_sync(fa0, &tb[buf][(r0)      * BPITCH + kk], BPITCH);
            wmma::load_matrix_sync(fa1, &tb[buf][(r0 + 16) * BPITCH + kk], BPITCH);
            wmma::load_matrix_sync(fb0, &tb[buf][(q0)      * BPITCH + kk], BPITCH);
            wmma::load_matrix_sync(fb1, &tb[buf][(q0 + 16) * BPITCH + kk], BPITCH);
            wmma::mma_sync(acc[0][0], fa0, fb0, acc[0][0]);
            wmma::mma_sync(acc[0][1], fa0, fb1, acc[0][1]);
            wmma::mma_sync(acc[1][0], fa1, fb0, acc[1][0]);
            wmma::mma_sync(acc[1][1], fa1, fb1, acc[1][1]);
        }

        if (has) {
            #pragma unroll
            for (int j = 0; j < 4; ++j) {
                lsum += w[j].x + w[j].y + w[j].z + w[j].w;
                __nv_bfloat162* dst = (__nv_bfloat162*)&tb[buf ^ 1][row * BPITCH + (c4 + j) * 4];
                dst[0] = __floats2bfloat162_rn(w[j].x, w[j].y);
                dst[1] = __floats2bfloat162_rn(w[j].z, w[j].w);
            }
        }
        __syncthreads();
    }

    lsum += __shfl_down_sync(0xffffffffu, lsum, 2);
    lsum += __shfl_down_sync(0xffffffffu, lsum, 1);
    if ((t & 3) == 0) ssum[row] = lsum;

    if (khalf == 1) {
        #pragma unroll
        for (int i = 0; i < 2; ++i)
            #pragma unroll
            for (int j = 0; j < 2; ++j)
                wmma::store_matrix_sync(&sred[quad][(16 * i) * RPITCH + 16 * j],
                                        acc[i][j], RPITCH, wmma::mem_row_major);
    }
    __syncthreads();

    if (khalf == 0) {
        #pragma unroll
        for (int i = 0; i < 2; ++i) {
            #pragma unroll
            for (int j = 0; j < 2; ++j) {
                wmma::fragment<wmma::accumulator, 16, 16, 16, float> tmp;
                wmma::load_matrix_sync(tmp, &sred[quad][(16 * i) * RPITCH + 16 * j],
                                       RPITCH, wmma::mem_row_major);
                #pragma unroll
                for (int e = 0; e < tmp.num_elements; ++e)
                    acc[i][j].x[e] += tmp.x[e];
                wmma::store_matrix_sync(&g_partials[b][(r0 + 16 * i) * 64 + q0 + 16 * j],
                                        acc[i][j], 64, wmma::mem_row_major);
            }
        }
    }
    if (t < NC) g_partials[b][4096 + t] = ssum[t];
}

// ---------------------------------------------------------------------------
// Kernel 2: reduce GRID_G partials -> g_G  (float4 vectorized)
// ---------------------------------------------------------------------------
__global__ __launch_bounds__(256) void reduce_kernel() {
    const int i4 = blockIdx.x * blockDim.x + threadIdx.x;
    if (i4 < 1040) {
        float4 s = make_float4(0.f, 0.f, 0.f, 0.f);
        #pragma unroll 4
        for (int b = 0; b < GRID_G; ++b) {
            float4 v = ((const float4*)g_partials[b])[i4];
            s.x += v.x; s.y += v.y; s.z += v.z; s.w += v.w;
        }
        ((float4*)g_G)[i4] = s;
    }
}

// ---------------------------------------------------------------------------
// Kernel 3: stats: sigma -> Taylor inverse-sqrt -> E, emitted in the
// lane-major permuted uint4 layout the whiten kernel consumes.
// ---------------------------------------------------------------------------
__global__ __launch_bounds__(256) void stats_kernel() {
    __shared__ float sP[4096];
    __shared__ float sQ[4096];
    __shared__ float smean[NC];
    __shared__ float sMu, sRs;

    const int t = threadIdx.x;
    const float invm = 1.0f / (float)MTOT;

    if (t < NC) {
        float mn = g_G[4096 + t] * invm;
        smean[t] = mn;
        g_mean[t] = mn;
    }
    __syncthreads();

    for (int i = t; i < 4096; i += 256) {
        int r = i >> 6, c = i & 63;
        sP[i] = g_G[i] * invm - smean[r] * smean[c] + ((r == c) ? EPSF : 0.0f);
    }
    __syncthreads();

    if (t == 0) {
        float tr = 0.0f;
        for (int i = 0; i < NC; ++i) tr += sP[i * 65];
        float mu = tr / (float)NC;
        sMu = mu;
        float rs = rsqrtf(mu);
        rs = rs * (1.5f - 0.5f * mu * rs * rs);
        sRs = rs;
    }
    __syncthreads();

    const float invmu = 1.0f / sMu;
    for (int i = t; i < 4096; i += 256) {
        int r = i >> 6, c = i & 63;
        sP[i] = sP[i] * invmu - ((r == c) ? 1.0f : 0.0f);
    }
    __syncthreads();

    const int r0 = (t >> 4) * 4;
    const int c0 = (t & 15) * 4;
    {
        float a[4][4] = {};
        for (int k = 0; k < 64; ++k) {
            float pa[4], pb[4];
            #pragma unroll
            for (int i = 0; i < 4; ++i) pa[i] = sP[(r0 + i) * 64 + k];
            #pragma unroll
            for (int j = 0; j < 4; ++j) pb[j] = sP[k * 64 + c0 + j];
            #pragma unroll
            for (int i = 0; i < 4; ++i)
                #pragma unroll
                for (int j = 0; j < 4; ++j) a[i][j] += pa[i] * pb[j];
        }
        #pragma unroll
        for (int i = 0; i < 4; ++i)
            #pragma unroll
            for (int j = 0; j < 4; ++j) sQ[(r0 + i) * 64 + c0 + j] = a[i][j];
    }
    __syncthreads();

    // E = wm - I (fp32), buffered in registers, then published into sQ
    const float rs = sRs;
    float efreg[4][4];
    {
        float a[4][4] = {};
        for (int k = 0; k < 64; ++k) {
            float pa[4], pb[4];
            #pragma unroll
            for (int i = 0; i < 4; ++i) pa[i] = sQ[(r0 + i) * 64 + k];
            #pragma unroll
            for (int j = 0; j < 4; ++j) pb[j] = sP[k * 64 + c0 + j];
            #pragma unroll
            for (int i = 0; i < 4; ++i)
                #pragma unroll
                for (int j = 0; j < 4; ++j) a[i][j] += pa[i] * pb[j];
        }
        #pragma unroll
        for (int i = 0; i < 4; ++i) {
            #pragma unroll
            for (int j = 0; j < 4; ++j) {
                int idx = (r0 + i) * 64 + (c0 + j);
                float dlt = (r0 + i == c0 + j) ? 1.0f : 0.0f;
                float wmh = dlt - 0.5f * sP[idx] + 0.375f * sQ[idx] - 0.3125f * a[i][j];
                efreg[i][j] = wmh * rs - dlt;
            }
        }
    }
    __syncthreads();   // everyone done READING sQ
    #pragma unroll
    for (int i = 0; i < 4; ++i)
        #pragma unroll
        for (int j = 0; j < 4; ++j)
            sQ[(r0 + i) * 64 + (c0 + j)] = efreg[i][j];
    __syncthreads();   // fp32 E now in sQ

    // permuted emit: thread t = (nb, lane); row = nb*8+g, cols kb*16+tg*2 (+8)
    {
        const int nb = t >> 5, lane = t & 31;
        const int g = lane >> 2, tg = lane & 3;
        const int row = nb * 8 + g;
        uint32_t pa[4], pb[4];
        #pragma unroll
        for (int kb = 0; kb < 4; ++kb) {
            const int col = kb * 16 + tg * 2;
            pa[kb] = pack_bf16x2(sQ[row * 64 + col],     sQ[row * 64 + col + 1]);
            pb[kb] = pack_bf16x2(sQ[row * 64 + col + 8], sQ[row * 64 + col + 9]);
        }
        g_EpA[nb][lane] = make_uint4(pa[0], pa[1], pa[2], pa[3]);
        g_EpB[nb][lane] = make_uint4(pb[0], pb[1], pb[2], pb[3]);
    }
}

// ---------------------------------------------------------------------------
// Kernel 4: whiten, warp-independent PTX mma. E now lives in smem in the
// lane-major permuted layout: per n-block, each lane fetches its B fragments
// with 2 conflict-free LDS.128. Register count drops ~127 -> ~65, enabling
// 3 CTAs/SM (GRID_W = 444, one wave).
// ---------------------------------------------------------------------------
__global__ __launch_bounds__(256, 3) void whiten_kernel(const float* __restrict__ X,
                                                        float* __restrict__ Y) {
    __shared__ __align__(16) __nv_bfloat16 wtile[8][NC * TPITCH];  // 3KB/warp
    __shared__ uint4 sEpA[8][32];   // 4KB
    __shared__ uint4 sEpB[8][32];   // 4KB
    __shared__ float smean[NC];

    const int t = threadIdx.x, b = blockIdx.x;
    const int warp = t >> 5, lane = t & 31;
    const int g  = lane >> 2;      // groupID 0..7
    const int tg = lane & 3;       // threadID_in_group

    if (t < NC) smean[t] = g_mean[t];
    sEpA[t >> 5][t & 31] = g_EpA[t >> 5][t & 31];
    sEpB[t >> 5][t & 31] = g_EpB[t >> 5][t & 31];
    __syncthreads();   // the only block barrier

    __nv_bfloat16* tile = wtile[warp];

    // loader mapping: lane pair (cl,o) owns channel rows cl+bi*16
    const int cl = lane >> 1;
    const int o  = lane & 1;
    float mus[4];
    #pragma unroll
    for (int bi = 0; bi < 4; ++bi) mus[bi] = smean[cl + bi * 16];

    // ldmatrix lane address (A^T rows = k-rows of the tile)
    const int kq = lane >> 4;
    const int c_base = kq * 8 + (lane & 7);
    const int s_off  = ((lane >> 3) & 1) * 8;
    const uint32_t lm_base =
        (uint32_t)__cvta_generic_to_shared(tile + c_base * TPITCH + s_off);

    const int W = b * 8 + warp;

    for (int S = W; S < NSLICE; S += NWARPS) {
        const int n  = S / 196;
        const int sc = (S % 196) * 16;
        const float* base = X + (size_t)n * NC * SS + sc;
        float*       yb   = Y + (size_t)n * NC * SS + sc;

        __syncwarp();  // prior slice's ldmatrix fully drained

        // load 64ch x 16s, center, bf16 into warp tile (4 passes of 16 ch)
        #pragma unroll
        for (int bi = 0; bi < 4; ++bi) {
            const int c = cl + bi * 16;
            const float mu = mus[bi];
            const float* p = base + (size_t)c * SS + o * 4;
            float4 v0 = *(const float4*)(p);
            float4 v1 = *(const float4*)(p + 8);
            v0.x -= mu; v0.y -= mu; v0.z -= mu; v0.w -= mu;
            v1.x -= mu; v1.y -= mu; v1.z -= mu; v1.w -= mu;
            __nv_bfloat162* dst = (__nv_bfloat162*)&tile[c * TPITCH + o * 4];
            dst[0] = __floats2bfloat162_rn(v0.x, v0.y);
            dst[1] = __floats2bfloat162_rn(v0.z, v0.w);
            dst[4] = __floats2bfloat162_rn(v1.x, v1.y);   // +8 bf16 = +4 b162
            dst[5] = __floats2bfloat162_rn(v1.z, v1.w);
        }
        __syncwarp();

        // A fragments: 4 k-blocks via ldmatrix.x4.trans
        uint32_t A[4][4];
        #pragma unroll
        for (int kb = 0; kb < 4; ++kb)
            ldmatrix_x4_trans(A[kb][0], A[kb][1], A[kb][2], A[kb][3],
                              lm_base + kb * 16 * TPITCH * 2);

        // 8 n-blocks; B fragments via 2 LDS.128; acc init = fp32 identity (xc)
        #pragma unroll
        for (int nb = 0; nb < 8; ++nb) {
            const uint4 ba = sEpA[nb][lane];
            const uint4 bb = sEpB[nb][lane];

            const int ca = nb * 8 + tg * 2;
            const float muA = smean[ca];
            const float muB = smean[ca + 1];
            const float* xa = base + (size_t)ca * SS;
            const float* xb = xa + SS;

            float c0 = xa[g]     - muA;
            float c1 = xb[g]     - muB;
            float c2 = xa[g + 8] - muA;
            float c3 = xb[g + 8] - muB;

            mma16816(c0, c1, c2, c3, A[0][0], A[0][1], A[0][2], A[0][3], ba.x, bb.x);
            mma16816(c0, c1, c2, c3, A[1][0], A[1][1], A[1][2], A[1][3], ba.y, bb.y);
            mma16816(c0, c1, c2, c3, A[2][0], A[2][1], A[2][2], A[2][3], ba.z, bb.z);
            mma16816(c0, c1, c2, c3, A[3][0], A[3][1], A[3][2], A[3][3], ba.w, bb.w);

            float* ya  = yb + (size_t)ca * SS;
            float* ybb = ya + SS;
            ya [g]     = c0;
            ybb[g]     = c1;
            ya [g + 8] = c2;
            ybb[g + 8] = c3;
        }
    }
}

// ---------------------------------------------------------------------------
extern "C" void kernel_launch(void* const* d_in, const int* in_sizes, int n_in,
                              void* d_out, int out_size) {
    (void)in_sizes; (void)n_in; (void)out_size;
    const float* X = (const float*)d_in[0];
    float* Y = (float*)d_out;

    gram_kernel<<<GRID_G, 256>>>(X);
    reduce_kernel<<<5, 256>>>();
    stats_kernel<<<1, 256>>>();
    whiten_kernel<<<GRID_W, 256>>>(X, Y);
}

// round 17
// speedup vs baseline: 1.4640x; 1.4640x over previous
#include <cuda_runtime.h>
#include <cuda_bf16.h>
#include <mma.h>
#include <cstdint>

using namespace nvcuda;

// Problem constants
#define NC     64          // channels
#define SS     3136        // 56*56
#define NIMG   128
#define MTOT   (NIMG*SS)   // 401408
#define KT     64          // s-tile width (gram)
#define TILES  (NIMG*49)   // 6272 tiles of 64 columns (gram)
#define GRID_G 296         // gram: one wave at 2 CTA/SM
#define GRID_W 296         // whiten: one wave at 2 CTA/SM
#define NWARPS (GRID_W*8)  // 2368 independent whiten warps
#define NSLICE (NIMG*196)  // 25088 slices of 64ch x 16s
#define BPITCH 72          // gram bf16 smem pitch
#define RPITCH 36          // gram reduction pitch
#define TPITCH 24          // whiten warp-tile bf16 pitch (48B rows)
#define EPSF   1e-3f

// Scratch (static device globals: allocation-free)
__device__ float          g_partials[GRID_G][4160]; // 4096 gram + 64 channel sums
__device__ float          g_G[4160];
__device__ float          g_mean[NC];
__device__ __nv_bfloat16  g_E[NC*NC];               // wm - I, row-major [c_out][c_in]

// ---------------------------------------------------------------------------
// PTX helpers (documented fragment layouts)
// ---------------------------------------------------------------------------
__device__ __forceinline__ void ldmatrix_x4_trans(uint32_t& r0, uint32_t& r1,
                                                  uint32_t& r2, uint32_t& r3,
                                                  uint32_t saddr) {
    asm volatile("ldmatrix.sync.aligned.m8n8.x4.trans.shared.b16 {%0,%1,%2,%3}, [%4];"
                 : "=r"(r0), "=r"(r1), "=r"(r2), "=r"(r3) : "r"(saddr));
}

__device__ __forceinline__ void mma16816(float& c0, float& c1, float& c2, float& c3,
                                         uint32_t a0, uint32_t a1, uint32_t a2, uint32_t a3,
                                         uint32_t b0, uint32_t b1) {
    asm volatile("mma.sync.aligned.m16n8k16.row.col.f32.bf16.bf16.f32 "
                 "{%0,%1,%2,%3},{%4,%5,%6,%7},{%8,%9},{%0,%1,%2,%3};"
                 : "+f"(c0), "+f"(c1), "+f"(c2), "+f"(c3)
                 : "r"(a0), "r"(a1), "r"(a2), "r"(a3), "r"(b0), "r"(b1));
}

// ---------------------------------------------------------------------------
// Kernel 1: partial Gram + channel sums. Warp = (kq, nhalf): m64 x n32 x k16
// per warp -> 6 fragment loads feed 8 MMAs per tile (was 8:8) => LDSM/tile
// drops 32KB -> 24KB. 64 acc regs/lane; one-time 4-stage k-reduction at end.
// Register prefetch + double buffer + one barrier per tile (measured wins).
// ---------------------------------------------------------------------------
__global__ __launch_bounds__(256, 2) void gram_kernel(const float* __restrict__ X) {
    __shared__ __nv_bfloat16 tb[2][NC * BPITCH];
    __shared__ float sred2[2][64 * RPITCH];   // per-nhalf 64x32 reduction buffer
    __shared__ float ssum[NC];

    const int t = threadIdx.x, b = blockIdx.x;
    const int warp = t >> 5;
    const int row = t >> 2;          // loader: channel row 0..63
    const int c4  = (t & 3) * 4;     // loader: first float4 index

    const int kq = warp >> 1;        // 0..3 : k-quarter (16 wide)
    const int nh = warp & 1;         // 0..1 : n-half (32 wide)
    const int q0 = nh * 32;
    const int kk = kq * 16;

    wmma::fragment<wmma::accumulator, 16, 16, 16, float> acc[4][2];
    #pragma unroll
    for (int i = 0; i < 4; ++i)
        #pragma unroll
        for (int j = 0; j < 2; ++j)
            wmma::fill_fragment(acc[i][j], 0.0f);

    float lsum = 0.0f;

    // prologue: tile b -> tb[0]
    {
        const int n  = b / 49;
        const int s0 = (b % 49) * KT;
        const float4* src = (const float4*)(X + (size_t)n * NC * SS + (size_t)row * SS + s0);
        #pragma unroll
        for (int j = 0; j < 4; ++j) {
            float4 v = src[c4 + j];
            lsum += v.x + v.y + v.z + v.w;
            __nv_bfloat162* dst = (__nv_bfloat162*)&tb[0][row * BPITCH + (c4 + j) * 4];
            dst[0] = __floats2bfloat162_rn(v.x, v.y);
            dst[1] = __floats2bfloat162_rn(v.z, v.w);
        }
    }
    __syncthreads();

    int buf = 0;
    for (int T = b; T < TILES; T += GRID_G, buf ^= 1) {
        const int Tn = T + GRID_G;
        const bool has = (Tn < TILES);

        // register prefetch of the next tile (in flight across the MMA)
        float4 w[4];
        if (has) {
            const int n  = Tn / 49;
            const int s0 = (Tn % 49) * KT;
            const float4* src = (const float4*)(X + (size_t)n * NC * SS + (size_t)row * SS + s0);
            #pragma unroll
            for (int j = 0; j < 4; ++j) w[j] = src[c4 + j];
        }

        // m64 x n32 over this warp's k-quarter: 2 fb + 4 fa loads, 8 MMAs
        {
            wmma::fragment<wmma::matrix_b, 16, 16, 16, __nv_bfloat16, wmma::col_major> fb0, fb1;
            wmma::load_matrix_sync(fb0, &tb[buf][(q0)      * BPITCH + kk], BPITCH);
            wmma::load_matrix_sync(fb1, &tb[buf][(q0 + 16) * BPITCH + kk], BPITCH);
            #pragma unroll
            for (int i = 0; i < 4; ++i) {
                wmma::fragment<wmma::matrix_a, 16, 16, 16, __nv_bfloat16, wmma::row_major> fa;
                wmma::load_matrix_sync(fa, &tb[buf][(i * 16) * BPITCH + kk], BPITCH);
                wmma::mma_sync(acc[i][0], fa, fb0, acc[i][0]);
                wmma::mma_sync(acc[i][1], fa, fb1, acc[i][1]);
            }
        }

        if (has) {
            #pragma unroll
            for (int j = 0; j < 4; ++j) {
                lsum += w[j].x + w[j].y + w[j].z + w[j].w;
                __nv_bfloat162* dst = (__nv_bfloat162*)&tb[buf ^ 1][row * BPITCH + (c4 + j) * 4];
                dst[0] = __floats2bfloat162_rn(w[j].x, w[j].y);
                dst[1] = __floats2bfloat162_rn(w[j].z, w[j].w);
            }
        }
        __syncthreads();
    }

    // channel-sum reduce: 4 consecutive lanes share a row
    lsum += __shfl_down_sync(0xffffffffu, lsum, 2);
    lsum += __shfl_down_sync(0xffffffffu, lsum, 1);
    if ((t & 3) == 0) ssum[row] = lsum;

    // 4-stage k-reduction: kq3 stores, kq2/kq1 add-in-place, kq0 finalizes
    if (kq == 3) {
        #pragma unroll
        for (int i = 0; i < 4; ++i)
            #pragma unroll
            for (int j = 0; j < 2; ++j)
                wmma::store_matrix_sync(&sred2[nh][(16 * i) * RPITCH + 16 * j],
                                        acc[i][j], RPITCH, wmma::mem_row_major);
    }
    __syncthreads();
    #pragma unroll
    for (int stage = 2; stage >= 1; --stage) {
        if (kq == stage) {
            #pragma unroll
            for (int i = 0; i < 4; ++i)
                #pragma unroll
                for (int j = 0; j < 2; ++j) {
                    wmma::fragment<wmma::accumulator, 16, 16, 16, float> tmp;
                    wmma::load_matrix_sync(tmp, &sred2[nh][(16 * i) * RPITCH + 16 * j],
                                           RPITCH, wmma::mem_row_major);
                    #pragma unroll
                    for (int e = 0; e < tmp.num_elements; ++e)
                        tmp.x[e] += acc[i][j].x[e];
                    wmma::store_matrix_sync(&sred2[nh][(16 * i) * RPITCH + 16 * j],
                                            tmp, RPITCH, wmma::mem_row_major);
                }
        }
        __syncthreads();
    }
    if (kq == 0) {
        #pragma unroll
        for (int i = 0; i < 4; ++i)
            #pragma unroll
            for (int j = 0; j < 2; ++j) {
                wmma::fragment<wmma::accumulator, 16, 16, 16, float> tmp;
                wmma::load_matrix_sync(tmp, &sred2[nh][(16 * i) * RPITCH + 16 * j],
                                       RPITCH, wmma::mem_row_major);
                #pragma unroll
                for (int e = 0; e < tmp.num_elements; ++e)
                    acc[i][j].x[e] += tmp.x[e];
                wmma::store_matrix_sync(&g_partials[b][(16 * i) * 64 + q0 + 16 * j],
                                        acc[i][j], 64, wmma::mem_row_major);
            }
    }
    if (t < NC) g_partials[b][4096 + t] = ssum[t];
}

// ---------------------------------------------------------------------------
// Kernel 2: reduce GRID_G partials -> g_G  (float4 vectorized)
// ---------------------------------------------------------------------------
__global__ __launch_bounds__(256) void reduce_kernel() {
    const int i4 = blockIdx.x * blockDim.x + threadIdx.x;
    if (i4 < 1040) {
        float4 s = make_float4(0.f, 0.f, 0.f, 0.f);
        #pragma unroll 4
        for (int b = 0; b < GRID_G; ++b) {
            float4 v = ((const float4*)g_partials[b])[i4];
            s.x += v.x; s.y += v.y; s.z += v.z; s.w += v.w;
        }
        ((float4*)g_G)[i4] = s;
    }
}

// ---------------------------------------------------------------------------
// Kernel 3: single-block stats: sigma -> Taylor inverse-sqrt -> E = wm - I
// ---------------------------------------------------------------------------
__global__ __launch_bounds__(256) void stats_kernel() {
    __shared__ float sP[4096];
    __shared__ float sQ[4096];
    __shared__ float smean[NC];
    __shared__ float sMu, sRs;

    const int t = threadIdx.x;
    const float invm = 1.0f / (float)MTOT;

    if (t < NC) {
        float mn = g_G[4096 + t] * invm;
        smean[t] = mn;
        g_mean[t] = mn;
    }
    __syncthreads();

    for (int i = t; i < 4096; i += 256) {
        int r = i >> 6, c = i & 63;
        sP[i] = g_G[i] * invm - smean[r] * smean[c] + ((r == c) ? EPSF : 0.0f);
    }
    __syncthreads();

    if (t == 0) {
        float tr = 0.0f;
        for (int i = 0; i < NC; ++i) tr += sP[i * 65];
        float mu = tr / (float)NC;
        sMu = mu;
        float rs = rsqrtf(mu);
        rs = rs * (1.5f - 0.5f * mu * rs * rs);
        sRs = rs;
    }
    __syncthreads();

    const float invmu = 1.0f / sMu;
    for (int i = t; i < 4096; i += 256) {
        int r = i >> 6, c = i & 63;
        sP[i] = sP[i] * invmu - ((r == c) ? 1.0f : 0.0f);
    }
    __syncthreads();

    const int r0 = (t >> 4) * 4;
    const int c0 = (t & 15) * 4;
    {
        float a[4][4] = {};
        for (int k = 0; k < 64; ++k) {
            float pa[4], pb[4];
            #pragma unroll
            for (int i = 0; i < 4; ++i) pa[i] = sP[(r0 + i) * 64 + k];
            #pragma unroll
            for (int j = 0; j < 4; ++j) pb[j] = sP[k * 64 + c0 + j];
            #pragma unroll
            for (int i = 0; i < 4; ++i)
                #pragma unroll
                for (int j = 0; j < 4; ++j) a[i][j] += pa[i] * pb[j];
        }
        #pragma unroll
        for (int i = 0; i < 4; ++i)
            #pragma unroll
            for (int j = 0; j < 4; ++j) sQ[(r0 + i) * 64 + c0 + j] = a[i][j];
    }
    __syncthreads();

    const float rs = sRs;
    {
        float a[4][4] = {};
        for (int k = 0; k < 64; ++k) {
            float pa[4], pb[4];
            #pragma unroll
            for (int i = 0; i < 4; ++i) pa[i] = sQ[(r0 + i) * 64 + k];
            #pragma unroll
            for (int j = 0; j < 4; ++j) pb[j] = sP[k * 64 + c0 + j];
            #pragma unroll
            for (int i = 0; i < 4; ++i)
                #pragma unroll
                for (int j = 0; j < 4; ++j) a[i][j] += pa[i] * pb[j];
        }
        #pragma unroll
        for (int i = 0; i < 4; ++i) {
            #pragma unroll
            for (int j = 0; j < 4; ++j) {
                int idx = (r0 + i) * 64 + (c0 + j);
                float dlt = (r0 + i == c0 + j) ? 1.0f : 0.0f;
                float wmh = dlt - 0.5f * sP[idx] + 0.375f * sQ[idx] - 0.3125f * a[i][j];
                g_E[idx] = __float2bfloat16(wmh * rs - dlt);
            }
        }
    }
}

// ---------------------------------------------------------------------------
// Kernel 4: whiten (R15 form, verbatim — measured best at 57.3us).
// Warp-independent PTX mma; E hoisted into 64 regs; direct-register epilogue.
// ---------------------------------------------------------------------------
__global__ __launch_bounds__(256, 2) void whiten_kernel(const float* __restrict__ X,
                                                        float* __restrict__ Y) {
    __shared__ __align__(16) __nv_bfloat16 wtile[8][NC * TPITCH];  // 3KB/warp
    __shared__ float smean[NC];

    const int t = threadIdx.x, b = blockIdx.x;
    const int warp = t >> 5, lane = t & 31;
    const int g  = lane >> 2;      // groupID 0..7
    const int tg = lane & 3;       // threadID_in_group

    if (t < NC) smean[t] = g_mean[t];
    __syncthreads();   // the only block barrier

    __nv_bfloat16* tile = wtile[warp];

    // hoisted B fragments: eb[kb][nb][i] ; b0=(k=tg*2,+1 | n=g), b1=(k+8)
    uint32_t eb[4][8][2];
    #pragma unroll
    for (int kb = 0; kb < 4; ++kb)
        #pragma unroll
        for (int nb = 0; nb < 8; ++nb) {
            const __nv_bfloat16* ep = g_E + (nb * 8 + g) * 64 + kb * 16 + tg * 2;
            eb[kb][nb][0] = *(const uint32_t*)(ep);
            eb[kb][nb][1] = *(const uint32_t*)(ep + 8);
        }

    // loader mapping: lane pair (cl,o) owns channel rows cl+bi*16
    const int cl = lane >> 1;
    const int o  = lane & 1;
    float mus[4];
    #pragma unroll
    for (int bi = 0; bi < 4; ++bi) mus[bi] = smean[cl + bi * 16];

    // ldmatrix lane address (A^T rows = k-rows of the tile)
    const int kq = lane >> 4;
    const int c_base = kq * 8 + (lane & 7);
    const int s_off  = ((lane >> 3) & 1) * 8;
    const uint32_t lm_base =
        (uint32_t)__cvta_generic_to_shared(tile + c_base * TPITCH + s_off);

    const int W = b * 8 + warp;

    for (int S = W; S < NSLICE; S += NWARPS) {
        const int n  = S / 196;
        const int sc = (S % 196) * 16;
        const float* base = X + (size_t)n * NC * SS + sc;
        float*       yb   = Y + (size_t)n * NC * SS + sc;

        __syncwarp();  // prior slice's ldmatrix fully drained

        // load 64ch x 16s, center, bf16 into warp tile (4 passes of 16 ch)
        #pragma unroll
        for (int bi = 0; bi < 4; ++bi) {
            const int c = cl + bi * 16;
            const float mu = mus[bi];
            const float* p = base + (size_t)c * SS + o * 4;
            float4 v0 = *(const float4*)(p);
            float4 v1 = *(const float4*)(p + 8);
            v0.x -= mu; v0.y -= mu; v0.z -= mu; v0.w -= mu;
            v1.x -= mu; v1.y -= mu; v1.z -= mu; v1.w -= mu;
            __nv_bfloat162* dst = (__nv_bfloat162*)&tile[c * TPITCH + o * 4];
            dst[0] = __floats2bfloat162_rn(v0.x, v0.y);
            dst[1] = __floats2bfloat162_rn(v0.z, v0.w);
            dst[4] = __floats2bfloat162_rn(v1.x, v1.y);   // +8 bf16 = +4 b162
            dst[5] = __floats2bfloat162_rn(v1.z, v1.w);
        }
        __syncwarp();

        // A fragments: 4 k-blocks via ldmatrix.x4.trans
        uint32_t A[4][4];
        #pragma unroll
        for (int kb = 0; kb < 4; ++kb)
            ldmatrix_x4_trans(A[kb][0], A[kb][1], A[kb][2], A[kb][3],
                              lm_base + kb * 16 * TPITCH * 2);

        // 8 n-blocks of 8 channels; acc initialized with fp32 identity (xc)
        #pragma unroll
        for (int nb = 0; nb < 8; ++nb) {
            const int ca = nb * 8 + tg * 2;
            const float muA = smean[ca];
            const float muB = smean[ca + 1];
            const float* xa = base + (size_t)ca * SS;
            const float* xb = xa + SS;

            float c0 = xa[g]     - muA;
            float c1 = xb[g]     - muB;
            float c2 = xa[g + 8] - muA;
            float c3 = xb[g + 8] - muB;

            #pragma unroll
            for (int kb = 0; kb < 4; ++kb)
                mma16816(c0, c1, c2, c3,
                         A[kb][0], A[kb][1], A[kb][2], A[kb][3],
                         eb[kb][nb][0], eb[kb][nb][1]);

            float* ya  = yb + (size_t)ca * SS;
            float* ybb = ya + SS;
            ya [g]     = c0;
            ybb[g]     = c1;
            ya [g + 8] = c2;
            ybb[g + 8] = c3;
        }
    }
}

// ---------------------------------------------------------------------------
extern "C" void kernel_launch(void* const* d_in, const int* in_sizes, int n_in,
                              void* d_out, int out_size) {
    (void)in_sizes; (void)n_in; (void)out_size;
    const float* X = (const float*)d_in[0];
    float* Y = (float*)d_out;

    gram_kernel<<<GRID_G, 256>>>(X);
    reduce_kernel<<<5, 256>>>();
    stats_kernel<<<1, 256>>>();
    whiten_kernel<<<GRID_W, 256>>>(X, Y);
}